// round 16
// baseline (speedup 1.0000x reference)
#include <cuda_runtime.h>

#define BATCH 4096

// ---------------- Device scratch ----------------
__device__ unsigned g_w1p[20];                         // 25 sign bits per filter
__device__ __align__(16) unsigned g_w2q[50*16];        // per filter: 500-bit window layout (p = t*20+c)
__device__ __align__(16) unsigned g_w3t[20*1024*4];    // w3 bits transposed: [wordblk i][neuron o][4 words]
__device__ unsigned g_w4p[10*32];                      // per out-neuron: 1024 sign bits
__device__ unsigned g_xrow[BATCH*64];                  // per image: [0..31]=mask rows, [32..63]=sign rows (bit xx+2)
__device__ unsigned g_packed1[BATCH*196];              // conv2 input: 20 ch bits per 14x14 pixel
__device__ __align__(16) unsigned g_packed2[BATCH*80]; // fc3 input bits (order pix*50+c), padded
__device__ unsigned g_packed3[BATCH*32];               // fc4 input bits (1024)

// ---------------- fused packing: w3 (coalesced read, transposed write) | xrow | small weights ----------------
// blocks [0,1024): w3 neuron per block | [1024,2048): xrow | [2048,2057): w1/w2q/w4
__global__ void __launch_bounds__(128) pack_all_kernel(const float* __restrict__ x,
                                                       const float* __restrict__ w1,
                                                       const float* __restrict__ w2,
                                                       const float* __restrict__ w3,
                                                       const float* __restrict__ w4) {
    int bid = blockIdx.x, tid = threadIdx.x;
    if (bid < 1024) {
        __shared__ unsigned char sb[2450];
        const float* row = w3 + bid * 2450;
        for (int j = tid; j < 2450; j += 128) sb[j] = (row[j] > 0.0f);
        __syncthreads();
        if (tid < 80) {
            unsigned m = 0; int base = tid * 32;
            for (int k = 0; k < 32; k++) {
                int jp = base + k;
                if (jp < 2450) {
                    int pix = jp / 50, c = jp % 50;   // orig flat index = c*49 + pix
                    m |= (unsigned)sb[c*49 + pix] << k;
                }
            }
            // transposed layout: word tid of neuron bid -> w3t[tid/4][bid][tid%4]
            g_w3t[(tid >> 2)*4096 + bid*4 + (tid & 3)] = m;
        }
    } else if (bid < 2048) {
        int id = (bid - 1024) * 128 + tid;            // 4096*32
        int b = id >> 5, r = id & 31;
        unsigned m = 0, p = 0;
        if (r >= 2 && r < 30) {
            const float* row = x + b*784 + (r-2)*28;
            #pragma unroll
            for (int xx = 0; xx < 28; xx++) {
                float v = row[xx];
                m |= (unsigned)(v != 0.0f) << (xx + 2);
                p |= (unsigned)(v > 0.0f)  << (xx + 2);
            }
        }
        g_xrow[b*64 + r]      = m;
        g_xrow[b*64 + 32 + r] = p;
    } else {
        int id = (bid - 2048) * 128 + tid;            // 1140 items
        if (id < 20) {
            unsigned m = 0;
            #pragma unroll
            for (int t = 0; t < 25; t++) m |= (unsigned)(w1[id*25 + t] > 0.0f) << t;
            g_w1p[id] = m;
        } else if (id < 820) {
            int idx = id - 20; int f = idx / 16, w = idx % 16;
            unsigned m = 0;
            for (int k = 0; k < 32; k++) {
                int p = w*32 + k;
                if (p < 500) {
                    int t = p / 20, c = p % 20;
                    m |= (unsigned)(w2[f*500 + c*25 + t] > 0.0f) << k;
                }
            }
            g_w2q[idx] = m;
        } else if (id < 1140) {
            int idx = id - 820; int o = idx / 32, w = idx % 32;
            unsigned m = 0;
            #pragma unroll
            for (int k = 0; k < 32; k++) m |= (unsigned)(w4[o*1024 + w*32 + k] > 0.0f) << k;
            g_w4p[idx] = m;
        }
    }
}

// ---------------- conv1 + relu + maxpool2 + sign -> packed channel bits ----------------
__global__ void __launch_bounds__(128) conv1_kernel(const float* __restrict__ b1) {
    __shared__ unsigned w1s[20];
    __shared__ float b1s[20];
    int tid = threadIdx.x;
    if (tid < 20) { w1s[tid] = g_w1p[tid]; b1s[tid] = b1[tid]; }
    __syncthreads();

    int id = blockIdx.x * 128 + tid;                 // 6272*128 = 4096*196
    if (id < BATCH*80) g_packed2[id] = 0;            // zero fc3-input rows for conv2's atomicOr
    int b = id / 196, pix = id % 196;
    int py = pix / 14, px = pix % 14;
    const unsigned* xr = g_xrow + b*64;

    unsigned mr[6], pr[6];
    #pragma unroll
    for (int i = 0; i < 6; i++) { mr[i] = xr[2*py + i]; pr[i] = xr[32 + 2*py + i]; }

    unsigned M[4], P[4]; int pm[4];
    #pragma unroll
    for (int dy = 0; dy < 2; dy++)
    #pragma unroll
    for (int dx = 0; dx < 2; dx++) {
        int sh = 2*px + dx;
        unsigned m = 0, p = 0;
        #pragma unroll
        for (int ky = 0; ky < 5; ky++) {
            m |= ((mr[dy + ky] >> sh) & 31u) << (5*ky);
            p |= ((pr[dy + ky] >> sh) & 31u) << (5*ky);
        }
        int w = dy*2 + dx;
        M[w] = m; P[w] = p; pm[w] = __popc(m);
    }

    unsigned word = 0;
    #pragma unroll
    for (int c = 0; c < 20; c++) {
        unsigned wp = w1s[c];
        int d0 = 2*__popc(M[0] & ~(P[0] ^ wp)) - pm[0];
        int d1 = 2*__popc(M[1] & ~(P[1] ^ wp)) - pm[1];
        int d2 = 2*__popc(M[2] & ~(P[2] ^ wp)) - pm[2];
        int d3 = 2*__popc(M[3] & ~(P[3] ^ wp)) - pm[3];
        int mx = max(max(d0, d1), max(d2, d3));
        if ((float)mx + b1s[c] > 0.0f) word |= 1u << c;
    }
    g_packed1[id] = word;
}

// ---------------- conv2: dense 512-bit window packing (best measured: 162.3us) ----------------
template<int BASE>
__device__ __forceinline__ void pack_window(const unsigned iw[36], unsigned W[16]) {
    unsigned long long acc = 0; int off = 0; int wi = 0;
    #pragma unroll
    for (int ky = 0; ky < 5; ky++) {
        #pragma unroll
        for (int kx = 0; kx < 5; kx++) {
            unsigned long long v = iw[BASE + ky*6 + kx];
            acc |= v << off;
            off += 20;
            if (off >= 32) { W[wi++] = (unsigned)acc; acc >>= 32; off -= 32; }
        }
    }
    W[wi] = (unsigned)acc;
}

__global__ void __launch_bounds__(128) conv2_kernel(const float* __restrict__ b2) {
    __shared__ __align__(16) unsigned sw[50*16];
    __shared__ float b2s[50];
    int tid = threadIdx.x;
    for (int t = tid; t < 800; t += 128) sw[t] = g_w2q[t];
    if (tid < 50) b2s[tid] = b2[tid];
    __syncthreads();

    int id = blockIdx.x * 128 + tid;                 // 1568*128 = 4096*49
    int b = id / 49, pix = id % 49;
    int py = pix / 7, px = pix % 7;
    const unsigned* inb = g_packed1 + b * 196;

    unsigned iw[36];
    #pragma unroll
    for (int i = 0; i < 6; i++) {
        int y = py*2 - 2 + i;
        #pragma unroll
        for (int j = 0; j < 6; j++) {
            int xx = px*2 - 2 + j;
            unsigned v = 0u;
            if ((unsigned)y < 14u && (unsigned)xx < 14u) v = inb[y*14 + xx];
            iw[i*6+j] = v;
        }
    }

    unsigned W0[16], W1[16], W2[16], W3[16];
    pack_window<0>(iw, W0);
    pack_window<1>(iw, W1);
    pack_window<6>(iw, W2);
    pack_window<7>(iw, W3);

    int S0=0,S1=0,S2=0,S3=0;
    #pragma unroll
    for (int j = 0; j < 16; j++) {
        S0 += __popc(W0[j]); S1 += __popc(W1[j]);
        S2 += __popc(W2[j]); S3 += __popc(W3[j]);
    }

    unsigned long long bits = 0ull;
    for (int f = 0; f < 50; f++) {
        const uint4* fp = (const uint4*)&sw[f*16];
        int P0=0,P1=0,P2=0,P3=0;
        #pragma unroll
        for (int q = 0; q < 4; q++) {
            uint4 w = fp[q];
            unsigned fw[4] = {w.x, w.y, w.z, w.w};
            #pragma unroll
            for (int k = 0; k < 4; k++) {
                int j = q*4 + k;
                P0 += __popc(W0[j] & fw[k]);
                P1 += __popc(W1[j] & fw[k]);
                P2 += __popc(W2[j] & fw[k]);
                P3 += __popc(W3[j] & fw[k]);
            }
        }
        int mx = max(max(2*P0 - S0, 2*P1 - S1), max(2*P2 - S2, 2*P3 - S3));
        bits |= (unsigned long long)((float)mx + b2s[f] > 0.0f) << f;
    }

    unsigned* row = g_packed2 + b * 80;
    int base = pix * 50;
    int w0 = base >> 5, sh = base & 31;
    unsigned long long lo = bits << sh;
    atomicOr(&row[w0],     (unsigned)lo);
    atomicOr(&row[w0 + 1], (unsigned)(lo >> 32));
    if (sh >= 15) atomicOr(&row[w0 + 2], (unsigned)(bits >> (64 - sh)));
}

// ---------------- fc3: 2 outputs x 8 batches, coalesced transposed w3 loads ----------------
__global__ void __launch_bounds__(128) fc3_kernel(const float* __restrict__ b3) {
    __shared__ __align__(16) unsigned sa[8*80];
    __shared__ int sna[8];
    int tid = threadIdx.x;
    int b0 = blockIdx.y * 8;
    for (int t = tid; t < 160; t += 128)
        ((uint4*)sa)[t] = ((const uint4*)(g_packed2 + b0*80))[t];
    __syncthreads();
    if (tid < 8) {
        int s = 0;
        #pragma unroll 8
        for (int i = 0; i < 80; i++) s += __popc(sa[tid*80 + i]);
        sna[tid] = s;
    }
    __syncthreads();

    int obase = blockIdx.x * 256 + tid;              // outputs obase, obase+128
    const uint4* w3t = (const uint4*)g_w3t;          // [20][1024] uint4

    int cnt[2][8];
    #pragma unroll
    for (int j = 0; j < 2; j++)
        #pragma unroll
        for (int bb = 0; bb < 8; bb++) cnt[j][bb] = 0;

    #pragma unroll 2
    for (int i = 0; i < 20; i++) {
        uint4 w0 = w3t[i*1024 + obase];              // warp: 32 consecutive uint4 = 512B
        uint4 w1 = w3t[i*1024 + obase + 128];
        #pragma unroll
        for (int bb = 0; bb < 8; bb++) {
            uint4 a = *(const uint4*)&sa[bb*80 + i*4];
            cnt[0][bb] += __popc(a.x & w0.x) + __popc(a.y & w0.y)
                        + __popc(a.z & w0.z) + __popc(a.w & w0.w);
            cnt[1][bb] += __popc(a.x & w1.x) + __popc(a.y & w1.y)
                        + __popc(a.z & w1.z) + __popc(a.w & w1.w);
        }
    }

    #pragma unroll
    for (int j = 0; j < 2; j++) {
        int o = obase + 128*j;
        float bias = b3[o];
        int widx = o >> 5;
        #pragma unroll
        for (int bb = 0; bb < 8; bb++) {
            float val = (float)(2*cnt[j][bb] - sna[bb]) + bias;
            unsigned word = __ballot_sync(0xffffffffu, val > 0.0f);
            if ((tid & 31) == 0) g_packed3[(b0 + bb)*32 + widx] = word;
        }
    }
}

// ---------------- fc4 ----------------
__global__ void __launch_bounds__(128) fc4_kernel(const float* __restrict__ b4, float* __restrict__ out) {
    __shared__ unsigned w4s[10*32];
    __shared__ float b4s[10];
    int tid = threadIdx.x;
    for (int t = tid; t < 320; t += 128) w4s[t] = g_w4p[t];
    if (tid < 10) b4s[tid] = b4[tid];
    __syncthreads();

    int b = blockIdx.x * 128 + tid;                  // 32*128 = 4096
    unsigned a[32]; int na = 0;
    #pragma unroll
    for (int i = 0; i < 32; i++) { a[i] = g_packed3[b*32 + i]; na += __popc(a[i]); }
    #pragma unroll
    for (int k = 0; k < 10; k++) {
        int cnt = 0;
        #pragma unroll
        for (int i = 0; i < 32; i++) cnt += __popc(a[i] & w4s[k*32 + i]);
        out[b*10 + k] = (float)(2*cnt - na) + b4s[k];
    }
}

// ---------------- launch ----------------
extern "C" void kernel_launch(void* const* d_in, const int* in_sizes, int n_in,
                              void* d_out, int out_size) {
    const float* x  = (const float*)d_in[0];
    const float* w1 = (const float*)d_in[1];
    const float* b1 = (const float*)d_in[2];
    const float* w2 = (const float*)d_in[3];
    const float* b2 = (const float*)d_in[4];
    const float* w3 = (const float*)d_in[5];
    const float* b3 = (const float*)d_in[6];
    const float* w4 = (const float*)d_in[7];
    const float* b4 = (const float*)d_in[8];
    float* out = (float*)d_out;

    pack_all_kernel<<<2057, 128>>>(x, w1, w2, w3, w4);  // w3(transposed) | xrow | small weights
    conv1_kernel<<<6272, 128>>>(b1);                    // 4096*196 (+ zeroes g_packed2)
    conv2_kernel<<<1568, 128>>>(b2);                    // 4096*49
    fc3_kernel<<<dim3(4, 512), 128>>>(b3);              // 1024 outs x (4096/8), 2x8 tile
    fc4_kernel<<<32, 128>>>(b4, out);                   // 4096
}

// round 17
// speedup vs baseline: 1.2110x; 1.2110x over previous
#include <cuda_runtime.h>

#define BATCH 4096

// ---------------- Device scratch ----------------
__device__ unsigned g_w1p[20];                         // 25 sign bits per filter
__device__ __align__(16) unsigned g_w2q[50*16];        // per filter: 500-bit window layout (p = t*20+c)
__device__ __align__(16) unsigned g_w3t[20*1024*4];    // w3 bits transposed: [wordblk i][neuron o][4 words]
__device__ unsigned g_w4p[10*32];                      // per out-neuron: 1024 sign bits
__device__ unsigned g_xrow[BATCH*64];                  // per image: [0..31]=mask rows, [32..63]=sign rows (bit xx+2)
__device__ unsigned g_packed1[BATCH*196];              // conv2 input: 20 ch bits per 14x14 pixel
__device__ __align__(16) unsigned g_packed2[BATCH*80]; // fc3 input bits (order pix*50+c), padded
__device__ unsigned g_packed3[BATCH*32];               // fc4 input bits (1024)

// ---------------- fused packing: w3 (coalesced read, transposed write) | xrow | small weights ----------------
__global__ void __launch_bounds__(128) pack_all_kernel(const float* __restrict__ x,
                                                       const float* __restrict__ w1,
                                                       const float* __restrict__ w2,
                                                       const float* __restrict__ w3,
                                                       const float* __restrict__ w4) {
    int bid = blockIdx.x, tid = threadIdx.x;
    if (bid < 1024) {
        __shared__ unsigned char sb[2450];
        const float* row = w3 + bid * 2450;
        for (int j = tid; j < 2450; j += 128) sb[j] = (row[j] > 0.0f);
        __syncthreads();
        if (tid < 80) {
            unsigned m = 0; int base = tid * 32;
            for (int k = 0; k < 32; k++) {
                int jp = base + k;
                if (jp < 2450) {
                    int pix = jp / 50, c = jp % 50;   // orig flat index = c*49 + pix
                    m |= (unsigned)sb[c*49 + pix] << k;
                }
            }
            g_w3t[(tid >> 2)*4096 + bid*4 + (tid & 3)] = m;
        }
    } else if (bid < 2048) {
        int id = (bid - 1024) * 128 + tid;            // 4096*32
        int b = id >> 5, r = id & 31;
        unsigned m = 0, p = 0;
        if (r >= 2 && r < 30) {
            const float* row = x + b*784 + (r-2)*28;
            #pragma unroll
            for (int xx = 0; xx < 28; xx++) {
                float v = row[xx];
                m |= (unsigned)(v != 0.0f) << (xx + 2);
                p |= (unsigned)(v > 0.0f)  << (xx + 2);
            }
        }
        g_xrow[b*64 + r]      = m;
        g_xrow[b*64 + 32 + r] = p;
    } else {
        int id = (bid - 2048) * 128 + tid;            // 1140 items
        if (id < 20) {
            unsigned m = 0;
            #pragma unroll
            for (int t = 0; t < 25; t++) m |= (unsigned)(w1[id*25 + t] > 0.0f) << t;
            g_w1p[id] = m;
        } else if (id < 820) {
            int idx = id - 20; int f = idx / 16, w = idx % 16;
            unsigned m = 0;
            for (int k = 0; k < 32; k++) {
                int p = w*32 + k;
                if (p < 500) {
                    int t = p / 20, c = p % 20;
                    m |= (unsigned)(w2[f*500 + c*25 + t] > 0.0f) << k;
                }
            }
            g_w2q[idx] = m;
        } else if (id < 1140) {
            int idx = id - 820; int o = idx / 32, w = idx % 32;
            unsigned m = 0;
            #pragma unroll
            for (int k = 0; k < 32; k++) m |= (unsigned)(w4[o*1024 + w*32 + k] > 0.0f) << k;
            g_w4p[idx] = m;
        }
    }
}

// ---------------- conv1 ----------------
__global__ void __launch_bounds__(128) conv1_kernel(const float* __restrict__ b1) {
    __shared__ unsigned w1s[20];
    __shared__ float b1s[20];
    int tid = threadIdx.x;
    if (tid < 20) { w1s[tid] = g_w1p[tid]; b1s[tid] = b1[tid]; }
    __syncthreads();

    int id = blockIdx.x * 128 + tid;                 // 6272*128 = 4096*196
    if (id < BATCH*80) g_packed2[id] = 0;
    int b = id / 196, pix = id % 196;
    int py = pix / 14, px = pix % 14;
    const unsigned* xr = g_xrow + b*64;

    unsigned mr[6], pr[6];
    #pragma unroll
    for (int i = 0; i < 6; i++) { mr[i] = xr[2*py + i]; pr[i] = xr[32 + 2*py + i]; }

    unsigned M[4], P[4]; int pm[4];
    #pragma unroll
    for (int dy = 0; dy < 2; dy++)
    #pragma unroll
    for (int dx = 0; dx < 2; dx++) {
        int sh = 2*px + dx;
        unsigned m = 0, p = 0;
        #pragma unroll
        for (int ky = 0; ky < 5; ky++) {
            m |= ((mr[dy + ky] >> sh) & 31u) << (5*ky);
            p |= ((pr[dy + ky] >> sh) & 31u) << (5*ky);
        }
        int w = dy*2 + dx;
        M[w] = m; P[w] = p; pm[w] = __popc(m);
    }

    unsigned word = 0;
    #pragma unroll
    for (int c = 0; c < 20; c++) {
        unsigned wp = w1s[c];
        int d0 = 2*__popc(M[0] & ~(P[0] ^ wp)) - pm[0];
        int d1 = 2*__popc(M[1] & ~(P[1] ^ wp)) - pm[1];
        int d2 = 2*__popc(M[2] & ~(P[2] ^ wp)) - pm[2];
        int d3 = 2*__popc(M[3] & ~(P[3] ^ wp)) - pm[3];
        int mx = max(max(d0, d1), max(d2, d3));
        if ((float)mx + b1s[c] > 0.0f) word |= 1u << c;
    }
    g_packed1[id] = word;
}

// ---------------- conv2: popc/CSA hybrid (8 direct popc + CSA-compressed 8 words) ----------------
template<int BASE>
__device__ __forceinline__ void pack_window(const unsigned iw[36], unsigned W[16]) {
    unsigned long long acc = 0; int off = 0; int wi = 0;
    #pragma unroll
    for (int ky = 0; ky < 5; ky++) {
        #pragma unroll
        for (int kx = 0; kx < 5; kx++) {
            unsigned long long v = iw[BASE + ky*6 + kx];
            acc |= v << off;
            off += 20;
            if (off >= 32) { W[wi++] = (unsigned)acc; acc >>= 32; off -= 32; }
        }
    }
    W[wi] = (unsigned)acc;
}

// dot of 512-bit W with filter words: words 0-7 direct popc, words 8-15 via CSA tree (4 popc)
__device__ __forceinline__ int dotw(const unsigned* W, uint4 wa, uint4 wb, uint4 wc, uint4 wd) {
    int P = __popc(W[0]&wa.x) + __popc(W[1]&wa.y) + __popc(W[2]&wa.z) + __popc(W[3]&wa.w)
          + __popc(W[4]&wb.x) + __popc(W[5]&wb.y) + __popc(W[6]&wb.z) + __popc(W[7]&wb.w);
    unsigned a0 = W[8]&wc.x,  a1 = W[9]&wc.y,  a2 = W[10]&wc.z, a3 = W[11]&wc.w;
    unsigned a4 = W[12]&wd.x, a5 = W[13]&wd.y, a6 = W[14]&wd.z, a7 = W[15]&wd.w;
    unsigned s1 = a0^a1^a2, c1 = (a0&a1)|(a0&a2)|(a1&a2);
    unsigned s2 = a3^a4^a5, c2 = (a3&a4)|(a3&a5)|(a4&a5);
    unsigned s3 = a6^a7^s1, c3 = (a6&a7)|(a6&s1)|(a7&s1);
    unsigned s4 = s2^s3,    c4 = s2&s3;
    unsigned s5 = c1^c2^c3, c5 = (c1&c2)|(c1&c3)|(c2&c3);
    unsigned s6 = s5^c4,    c6 = s5&c4;
    // sum(a0..a7) = s4 + 2*s6 + 4*(c5 + c6)
    return P + __popc(s4) + 2*__popc(s6) + 4*(__popc(c5) + __popc(c6));
}

__global__ void __launch_bounds__(128) conv2_kernel(const float* __restrict__ b2) {
    __shared__ __align__(16) unsigned sw[50*16];
    __shared__ float b2s[50];
    int tid = threadIdx.x;
    for (int t = tid; t < 800; t += 128) sw[t] = g_w2q[t];
    if (tid < 50) b2s[tid] = b2[tid];
    __syncthreads();

    int id = blockIdx.x * 128 + tid;                 // 1568*128 = 4096*49
    int b = id / 49, pix = id % 49;
    int py = pix / 7, px = pix % 7;
    const unsigned* inb = g_packed1 + b * 196;

    unsigned iw[36];
    #pragma unroll
    for (int i = 0; i < 6; i++) {
        int y = py*2 - 2 + i;
        #pragma unroll
        for (int j = 0; j < 6; j++) {
            int xx = px*2 - 2 + j;
            unsigned v = 0u;
            if ((unsigned)y < 14u && (unsigned)xx < 14u) v = inb[y*14 + xx];
            iw[i*6+j] = v;
        }
    }

    unsigned W0[16], W1[16], W2[16], W3[16];
    pack_window<0>(iw, W0);
    pack_window<1>(iw, W1);
    pack_window<6>(iw, W2);
    pack_window<7>(iw, W3);

    int S0=0,S1=0,S2=0,S3=0;
    #pragma unroll
    for (int j = 0; j < 16; j++) {
        S0 += __popc(W0[j]); S1 += __popc(W1[j]);
        S2 += __popc(W2[j]); S3 += __popc(W3[j]);
    }

    unsigned long long bits = 0ull;
    for (int f = 0; f < 50; f++) {
        const uint4* fp = (const uint4*)&sw[f*16];
        uint4 wa = fp[0], wb = fp[1], wc = fp[2], wd = fp[3];
        int P0 = dotw(W0, wa, wb, wc, wd);
        int P1 = dotw(W1, wa, wb, wc, wd);
        int P2 = dotw(W2, wa, wb, wc, wd);
        int P3 = dotw(W3, wa, wb, wc, wd);
        int mx = max(max(2*P0 - S0, 2*P1 - S1), max(2*P2 - S2, 2*P3 - S3));
        bits |= (unsigned long long)((float)mx + b2s[f] > 0.0f) << f;
    }

    unsigned* row = g_packed2 + b * 80;
    int base = pix * 50;
    int w0 = base >> 5, sh = base & 31;
    unsigned long long lo = bits << sh;
    atomicOr(&row[w0],     (unsigned)lo);
    atomicOr(&row[w0 + 1], (unsigned)(lo >> 32));
    if (sh >= 15) atomicOr(&row[w0 + 2], (unsigned)(bits >> (64 - sh)));
}

// ---------------- fc3: 2 outs x 8 batches, CSA-compressed popc (3 popc per 4 words) ----------------
__device__ __forceinline__ int dot4(uint4 a, uint4 w) {
    unsigned x0 = a.x & w.x, x1 = a.y & w.y, x2 = a.z & w.z, x3 = a.w & w.w;
    unsigned s  = x0^x1^x2, c = (x0&x1)|(x0&x2)|(x1&x2);
    unsigned s2 = s^x3,     c2 = s&x3;
    // x0+x1+x2+x3 = s2 + 2*(c + c2)
    return __popc(s2) + 2*(__popc(c) + __popc(c2));
}

__global__ void __launch_bounds__(128) fc3_kernel(const float* __restrict__ b3) {
    __shared__ __align__(16) unsigned sa[8*80];
    __shared__ int sna[8];
    int tid = threadIdx.x;
    int b0 = blockIdx.y * 8;
    for (int t = tid; t < 160; t += 128)
        ((uint4*)sa)[t] = ((const uint4*)(g_packed2 + b0*80))[t];
    __syncthreads();
    if (tid < 8) {
        int s = 0;
        #pragma unroll 8
        for (int i = 0; i < 80; i++) s += __popc(sa[tid*80 + i]);
        sna[tid] = s;
    }
    __syncthreads();

    int obase = blockIdx.x * 256 + tid;              // outputs obase, obase+128
    const uint4* w3t = (const uint4*)g_w3t;          // [20][1024] uint4

    int cnt[2][8];
    #pragma unroll
    for (int j = 0; j < 2; j++)
        #pragma unroll
        for (int bb = 0; bb < 8; bb++) cnt[j][bb] = 0;

    #pragma unroll 2
    for (int i = 0; i < 20; i++) {
        uint4 w0 = w3t[i*1024 + obase];
        uint4 w1 = w3t[i*1024 + obase + 128];
        #pragma unroll
        for (int bb = 0; bb < 8; bb++) {
            uint4 a = *(const uint4*)&sa[bb*80 + i*4];
            cnt[0][bb] += dot4(a, w0);
            cnt[1][bb] += dot4(a, w1);
        }
    }

    #pragma unroll
    for (int j = 0; j < 2; j++) {
        int o = obase + 128*j;
        float bias = b3[o];
        int widx = o >> 5;
        #pragma unroll
        for (int bb = 0; bb < 8; bb++) {
            float val = (float)(2*cnt[j][bb] - sna[bb]) + bias;
            unsigned word = __ballot_sync(0xffffffffu, val > 0.0f);
            if ((tid & 31) == 0) g_packed3[(b0 + bb)*32 + widx] = word;
        }
    }
}

// ---------------- fc4 ----------------
__global__ void __launch_bounds__(128) fc4_kernel(const float* __restrict__ b4, float* __restrict__ out) {
    __shared__ unsigned w4s[10*32];
    __shared__ float b4s[10];
    int tid = threadIdx.x;
    for (int t = tid; t < 320; t += 128) w4s[t] = g_w4p[t];
    if (tid < 10) b4s[tid] = b4[tid];
    __syncthreads();

    int b = blockIdx.x * 128 + tid;                  // 32*128 = 4096
    unsigned a[32]; int na = 0;
    #pragma unroll
    for (int i = 0; i < 32; i++) { a[i] = g_packed3[b*32 + i]; na += __popc(a[i]); }
    #pragma unroll
    for (int k = 0; k < 10; k++) {
        int cnt = 0;
        #pragma unroll
        for (int i = 0; i < 32; i++) cnt += __popc(a[i] & w4s[k*32 + i]);
        out[b*10 + k] = (float)(2*cnt - na) + b4s[k];
    }
}

// ---------------- launch ----------------
extern "C" void kernel_launch(void* const* d_in, const int* in_sizes, int n_in,
                              void* d_out, int out_size) {
    const float* x  = (const float*)d_in[0];
    const float* w1 = (const float*)d_in[1];
    const float* b1 = (const float*)d_in[2];
    const float* w2 = (const float*)d_in[3];
    const float* b2 = (const float*)d_in[4];
    const float* w3 = (const float*)d_in[5];
    const float* b3 = (const float*)d_in[6];
    const float* w4 = (const float*)d_in[7];
    const float* b4 = (const float*)d_in[8];
    float* out = (float*)d_out;

    pack_all_kernel<<<2057, 128>>>(x, w1, w2, w3, w4);  // w3(transposed) | xrow | small weights
    conv1_kernel<<<6272, 128>>>(b1);                    // 4096*196 (+ zeroes g_packed2)
    conv2_kernel<<<1568, 128>>>(b2);                    // 4096*49
    fc3_kernel<<<dim3(4, 512), 128>>>(b3);              // 1024 outs x (4096/8), 2x8 tile
    fc4_kernel<<<32, 128>>>(b4, out);                   // 4096
}